// round 15
// baseline (speedup 1.0000x reference)
#include <cuda_runtime.h>
#include <cuda_bf16.h>
#include <cstdint>
#include <math.h>

// Problem dims
#define NTOK   204800          // B*T*V = 64*128*25
#define NSEQ   8192            // B*T
#define SEQ    25
#define DMODEL 256
#define NHEAD  8
#define HDIM   32
#define DFFN   1024
#define D3     768

// ------------------------- scratch (device globals) -------------------------
__device__ __nv_bfloat16 g_yb  [(size_t)NTOK * DMODEL];   // LN1 output, bf16
__device__ __nv_bfloat16 g_qkv [(size_t)NTOK * D3];       // qkv, bf16
__device__ __nv_bfloat16 g_attn[(size_t)NTOK * DMODEL];   // attention out, bf16
__device__ float         g_x2  [(size_t)NTOK * DMODEL];   // residual after proj, fp32
__device__ __nv_bfloat16 g_y2  [(size_t)NTOK * DMODEL];   // LN2 output, bf16
__device__ __nv_bfloat16 g_hid [(size_t)NTOK * DFFN];     // ffn hidden, bf16
// weights stored TRANSPOSED: [N, K] K-major (B operand, row.col mma)
__device__ __nv_bfloat16 g_wqkv [D3   * DMODEL];
__device__ __nv_bfloat16 g_wproj[DMODEL * DMODEL];
__device__ __nv_bfloat16 g_w1   [DFFN * DMODEL];
__device__ __nv_bfloat16 g_w2   [DMODEL * DFFN];

// ------------------------- ptx helpers -------------------------
__device__ __forceinline__ void cp_async16(uint32_t smem_dst, const void* gmem_src) {
    asm volatile("cp.async.cg.shared.global [%0], [%1], 16;\n" :: "r"(smem_dst), "l"(gmem_src));
}
__device__ __forceinline__ void ldmatrix_x4(uint32_t& r0, uint32_t& r1, uint32_t& r2,
                                            uint32_t& r3, uint32_t addr) {
    asm volatile("ldmatrix.sync.aligned.m8n8.x4.shared.b16 {%0,%1,%2,%3}, [%4];"
                 : "=r"(r0), "=r"(r1), "=r"(r2), "=r"(r3) : "r"(addr));
}
__device__ __forceinline__ void mma16816(float& d0, float& d1, float& d2, float& d3,
                                         uint32_t a0, uint32_t a1, uint32_t a2, uint32_t a3,
                                         uint32_t b0, uint32_t b1) {
    asm volatile(
        "mma.sync.aligned.m16n8k16.row.col.f32.bf16.bf16.f32 "
        "{%0,%1,%2,%3}, {%4,%5,%6,%7}, {%8,%9}, {%0,%1,%2,%3};"
        : "+f"(d0), "+f"(d1), "+f"(d2), "+f"(d3)
        : "r"(a0), "r"(a1), "r"(a2), "r"(a3), "r"(b0), "r"(b1));
}

// ------------------------- tiled transpose + fp32->bf16 convert -----------------
// in: [K, N] fp32 row-major.  out: [N, K] bf16 row-major. Both sides coalesced.
__global__ __launch_bounds__(256) void transpose_convert(const float* __restrict__ in,
                                                         __nv_bfloat16* __restrict__ out,
                                                         int K, int N) {
    __shared__ float tile[32][33];
    int n0 = blockIdx.x * 32, k0 = blockIdx.y * 32;
    int tx = threadIdx.x, ty = threadIdx.y;
    #pragma unroll
    for (int r = 0; r < 4; r++)
        tile[ty + r * 8][tx] = in[(size_t)(k0 + ty + r * 8) * N + n0 + tx];
    __syncthreads();
    #pragma unroll
    for (int r = 0; r < 4; r++)
        out[(size_t)(n0 + ty + r * 8) * K + k0 + tx] = __float2bfloat16(tile[tx][ty + r * 8]);
}

// ------------------------- LayerNorm (warp per row, D=256) -------------------------
__global__ __launch_bounds__(256) void ln_kernel(const float* __restrict__ X,
                                                 const float* __restrict__ gam,
                                                 const float* __restrict__ bet,
                                                 __nv_bfloat16* __restrict__ Y) {
    int warp = (blockIdx.x * blockDim.x + threadIdx.x) >> 5;
    int lane = threadIdx.x & 31;
    if (warp >= NTOK) return;
    const float4* xp = (const float4*)(X + (size_t)warp * DMODEL);
    float4 v0 = xp[lane * 2];
    float4 v1 = xp[lane * 2 + 1];
    float s = v0.x + v0.y + v0.z + v0.w + v1.x + v1.y + v1.z + v1.w;
    #pragma unroll
    for (int o = 16; o > 0; o >>= 1) s += __shfl_xor_sync(0xffffffffu, s, o);
    float m = s * (1.0f / 256.0f);
    float d0x = v0.x - m, d0y = v0.y - m, d0z = v0.z - m, d0w = v0.w - m;
    float d1x = v1.x - m, d1y = v1.y - m, d1z = v1.z - m, d1w = v1.w - m;
    float vs = d0x*d0x + d0y*d0y + d0z*d0z + d0w*d0w + d1x*d1x + d1y*d1y + d1z*d1z + d1w*d1w;
    #pragma unroll
    for (int o = 16; o > 0; o >>= 1) vs += __shfl_xor_sync(0xffffffffu, vs, o);
    float rstd = rsqrtf(vs * (1.0f / 256.0f) + 1e-5f);
    const float4* gp = (const float4*)gam;
    const float4* bp = (const float4*)bet;
    float4 g0 = gp[lane * 2], g1 = gp[lane * 2 + 1];
    float4 b0 = bp[lane * 2], b1 = bp[lane * 2 + 1];
    float y[8];
    y[0] = d0x * rstd * g0.x + b0.x;  y[1] = d0y * rstd * g0.y + b0.y;
    y[2] = d0z * rstd * g0.z + b0.z;  y[3] = d0w * rstd * g0.w + b0.w;
    y[4] = d1x * rstd * g1.x + b1.x;  y[5] = d1y * rstd * g1.y + b1.y;
    y[6] = d1z * rstd * g1.z + b1.z;  y[7] = d1w * rstd * g1.w + b1.w;
    union { int4 i4; __nv_bfloat162 h2[4]; } u;
    u.h2[0] = __floats2bfloat162_rn(y[0], y[1]);
    u.h2[1] = __floats2bfloat162_rn(y[2], y[3]);
    u.h2[2] = __floats2bfloat162_rn(y[4], y[5]);
    u.h2[3] = __floats2bfloat162_rn(y[6], y[7]);
    *((int4*)(Y + (size_t)warp * DMODEL + lane * 8)) = u.i4;
}

// ------------------------- mma.sync GEMM (generic) -------------------------
// 128x128 CTA tile, BK=32, 4-stage cp.async pipeline, one barrier per chunk.
// 4 warps, warp tile 64x64.
enum { EPI_BF16 = 0, EPI_PROJ = 1, EPI_GELU = 2, EPI_OUT = 3 };

#define ROWB   80                    // padded row pitch in bytes (32 bf16 + 8 pad)
#define STAGE_A 10240                // 128 * 80
#define STAGE  20480                 // A + B per stage
#define NSTAGE 4
#define GSMEM  (NSTAGE * STAGE)      // 81920

template <int EPI>
__global__ __launch_bounds__(128) void mm_gemm(
    const __nv_bfloat16* __restrict__ A,
    const __nv_bfloat16* __restrict__ Bw,
    const float* __restrict__ bias,
    const float* __restrict__ res,
    void* __restrict__ out, int N, int K)
{
    extern __shared__ __align__(128) char smem[];
    const uint32_t sb = (uint32_t)__cvta_generic_to_shared(smem);
    const int t = threadIdx.x, wid = t >> 5, lane = t & 31;
    const int wm = wid & 1;
    const int wn = wid >> 1;
    const size_t m0 = (size_t)blockIdx.y * 128;
    const int n0 = blockIdx.x * 128;
    const int C = K >> 5;

    auto load_chunk = [&](int c, int s) {
        const uint32_t base = sb + (uint32_t)s * STAGE;
        const int k0 = c << 5;
        #pragma unroll
        for (int i = 0; i < 4; i++) {
            int idx = i * 128 + t;
            int r = idx >> 2, cc = idx & 3;
            cp_async16(base + (uint32_t)(r * ROWB + cc * 16),
                       A + (m0 + r) * K + k0 + cc * 8);
        }
        #pragma unroll
        for (int i = 0; i < 4; i++) {
            int idx = i * 128 + t;
            int r = idx >> 2, cc = idx & 3;
            cp_async16(base + STAGE_A + (uint32_t)(r * ROWB + cc * 16),
                       Bw + (size_t)(n0 + r) * K + k0 + cc * 8);
        }
        asm volatile("cp.async.commit_group;");
    };

    float acc[4][8][4];
    #pragma unroll
    for (int i = 0; i < 4; i++)
        #pragma unroll
        for (int j = 0; j < 8; j++)
            #pragma unroll
            for (int e = 0; e < 4; e++) acc[i][j][e] = 0.0f;

    load_chunk(0, 0);
    if (C > 1) load_chunk(1, 1);
    if (C > 2) load_chunk(2, 2);

    const int b_g = lane >> 3;
    const int b_row = lane & 7;
    const int b_noff = (b_g >> 1) * 8 + b_row;
    const int b_kc16 = (b_g & 1) * 16;

    for (int c = 0; c < C; c++) {
        if (c < C - 2)      { asm volatile("cp.async.wait_group 2;"); }
        else if (c == C - 2){ asm volatile("cp.async.wait_group 1;"); }
        else                { asm volatile("cp.async.wait_group 0;"); }
        __syncthreads();
        if (c + 3 < C) load_chunk(c + 3, (c + 3) & 3);

        const uint32_t aBase = sb + (uint32_t)(c & 3) * STAGE;
        const uint32_t bBase = aBase + STAGE_A;

        #pragma unroll
        for (int ks = 0; ks < 2; ks++) {
            uint32_t a[4][4];
            #pragma unroll
            for (int i = 0; i < 4; i++) {
                uint32_t addr = aBase
                    + (uint32_t)((wm * 64 + i * 16 + (lane & 15)) * ROWB
                                 + ks * 32 + (lane >> 4) * 16);
                ldmatrix_x4(a[i][0], a[i][1], a[i][2], a[i][3], addr);
            }
            uint32_t bb[8][2];
            #pragma unroll
            for (int g4 = 0; g4 < 4; g4++) {
                int nrow = wn * 64 + g4 * 16 + b_noff;
                uint32_t addr = bBase + (uint32_t)(nrow * ROWB + ks * 32 + b_kc16);
                ldmatrix_x4(bb[g4 * 2][0], bb[g4 * 2][1],
                            bb[g4 * 2 + 1][0], bb[g4 * 2 + 1][1], addr);
            }
            #pragma unroll
            for (int j = 0; j < 8; j++)
                #pragma unroll
                for (int i = 0; i < 4; i++)
                    mma16816(acc[i][j][0], acc[i][j][1], acc[i][j][2], acc[i][j][3],
                             a[i][0], a[i][1], a[i][2], a[i][3], bb[j][0], bb[j][1]);
        }
    }

    const int qrow = lane >> 2;
    const int qcol = (lane & 3) * 2;
    #pragma unroll
    for (int i = 0; i < 4; i++) {
        #pragma unroll
        for (int j = 0; j < 8; j++) {
            int col = n0 + wn * 64 + j * 8 + qcol;
            float2 bb = *(const float2*)(bias + col);
            #pragma unroll
            for (int h = 0; h < 2; h++) {
                size_t row = m0 + wm * 64 + i * 16 + qrow + h * 8;
                float v0 = acc[i][j][2 * h + 0] + bb.x;
                float v1 = acc[i][j][2 * h + 1] + bb.y;
                size_t o = row * (size_t)N + col;
                if (EPI == EPI_BF16) {
                    *(__nv_bfloat162*)((__nv_bfloat16*)out + o) = __floats2bfloat162_rn(v0, v1);
                } else if (EPI == EPI_GELU) {
                    v0 = 0.5f * v0 * (1.0f + erff(v0 * 0.70710678118654752f));
                    v1 = 0.5f * v1 * (1.0f + erff(v1 * 0.70710678118654752f));
                    *(__nv_bfloat162*)((__nv_bfloat16*)out + o) = __floats2bfloat162_rn(v0, v1);
                } else {
                    float2 rr = *(const float2*)(res + o);
                    float2 ov = make_float2(v0 + rr.x, v1 + rr.y);
                    *(float2*)((float*)out + o) = ov;
                }
            }
        }
    }
}

// ------------------------- proj GEMM + residual + fused LN2 -------------------------
// CTA tile 64x256 (4 warps, warp tile 64x64, wn = wid). N=256 covered entirely,
// so LN over the row is computed in-CTA. Writes x2 (fp32, pre-LN residual) and
// y2 (bf16, LN output).
#define PSTAGE_A (64 * ROWB)            // 5120
#define PSTAGE   (PSTAGE_A + 256 * ROWB) // 25600
#define PSMEM    (NSTAGE * PSTAGE)       // 102400

__global__ __launch_bounds__(128) void proj_ln_gemm(
    const __nv_bfloat16* __restrict__ A,     // g_attn
    const __nv_bfloat16* __restrict__ Bw,    // g_wproj [N,K]
    const float* __restrict__ bias,          // proj_b
    const float* __restrict__ res,           // x (input, fp32)
    const float* __restrict__ g2,            // ln2_g
    const float* __restrict__ be2,           // ln2_b
    float* __restrict__ x2,                  // out fp32
    __nv_bfloat16* __restrict__ y2)          // out bf16 (LN)
{
    const int NN = DMODEL, K = DMODEL;
    extern __shared__ __align__(128) char smem[];
    const uint32_t sb = (uint32_t)__cvta_generic_to_shared(smem);
    const int t = threadIdx.x, wid = t >> 5, lane = t & 31;
    const int wn = wid;                    // 0..3 -> 64-col slab
    const size_t m0 = (size_t)blockIdx.x * 64;
    const int C = K >> 5;                  // 8

    auto load_chunk = [&](int c, int s) {
        const uint32_t base = sb + (uint32_t)s * PSTAGE;
        const int k0 = c << 5;
        #pragma unroll
        for (int i = 0; i < 2; i++) {
            int idx = i * 128 + t;
            int r = idx >> 2, cc = idx & 3;
            cp_async16(base + (uint32_t)(r * ROWB + cc * 16),
                       A + (m0 + r) * K + k0 + cc * 8);
        }
        #pragma unroll
        for (int i = 0; i < 8; i++) {
            int idx = i * 128 + t;
            int r = idx >> 2, cc = idx & 3;
            cp_async16(base + PSTAGE_A + (uint32_t)(r * ROWB + cc * 16),
                       Bw + (size_t)r * K + k0 + cc * 8);
        }
        asm volatile("cp.async.commit_group;");
    };

    float acc[4][8][4];
    #pragma unroll
    for (int i = 0; i < 4; i++)
        #pragma unroll
        for (int j = 0; j < 8; j++)
            #pragma unroll
            for (int e = 0; e < 4; e++) acc[i][j][e] = 0.0f;

    load_chunk(0, 0);
    load_chunk(1, 1);
    load_chunk(2, 2);

    const int b_g = lane >> 3;
    const int b_row = lane & 7;
    const int b_noff = (b_g >> 1) * 8 + b_row;
    const int b_kc16 = (b_g & 1) * 16;

    for (int c = 0; c < C; c++) {
        if (c < C - 2)      { asm volatile("cp.async.wait_group 2;"); }
        else if (c == C - 2){ asm volatile("cp.async.wait_group 1;"); }
        else                { asm volatile("cp.async.wait_group 0;"); }
        __syncthreads();
        if (c + 3 < C) load_chunk(c + 3, (c + 3) & 3);

        const uint32_t aBase = sb + (uint32_t)(c & 3) * PSTAGE;
        const uint32_t bBase = aBase + PSTAGE_A;

        #pragma unroll
        for (int ks = 0; ks < 2; ks++) {
            uint32_t a[4][4];
            #pragma unroll
            for (int i = 0; i < 4; i++) {
                uint32_t addr = aBase
                    + (uint32_t)((i * 16 + (lane & 15)) * ROWB
                                 + ks * 32 + (lane >> 4) * 16);
                ldmatrix_x4(a[i][0], a[i][1], a[i][2], a[i][3], addr);
            }
            uint32_t bb[8][2];
            #pragma unroll
            for (int g4 = 0; g4 < 4; g4++) {
                int nrow = wn * 64 + g4 * 16 + b_noff;
                uint32_t addr = bBase + (uint32_t)(nrow * ROWB + ks * 32 + b_kc16);
                ldmatrix_x4(bb[g4 * 2][0], bb[g4 * 2][1],
                            bb[g4 * 2 + 1][0], bb[g4 * 2 + 1][1], addr);
            }
            #pragma unroll
            for (int j = 0; j < 8; j++)
                #pragma unroll
                for (int i = 0; i < 4; i++)
                    mma16816(acc[i][j][0], acc[i][j][1], acc[i][j][2], acc[i][j][3],
                             a[i][0], a[i][1], a[i][2], a[i][3], bb[j][0], bb[j][1]);
        }
    }

    // ---------------- epilogue: residual + x2 store + fused LN2 ----------------
    // red layout (floats over smem base, stage 0 region — not read by last chunks):
    //   [0..255]   s1 partials  [warp][row64]
    //   [256..511] s2 partials
    //   [512..575] mean per row
    //   [576..639] rstd per row
    float* red = (float*)smem;
    const int qrow = lane >> 2;
    const int qcol = (lane & 3) * 2;

    float s1[8], s2[8];
    #pragma unroll
    for (int tt = 0; tt < 8; tt++) { s1[tt] = 0.0f; s2[tt] = 0.0f; }

    // pass 1: v = acc + bias + residual; store x2; accumulate row sums
    #pragma unroll
    for (int i = 0; i < 4; i++) {
        #pragma unroll
        for (int j = 0; j < 8; j++) {
            int col = wn * 64 + j * 8 + qcol;
            float2 bv = *(const float2*)(bias + col);
            #pragma unroll
            for (int h = 0; h < 2; h++) {
                int tt = i * 2 + h;                 // row = qrow + 8*tt
                size_t row = m0 + (size_t)(qrow + 8 * tt);
                size_t o = row * (size_t)NN + col;
                float2 rr = *(const float2*)(res + o);
                float v0 = acc[i][j][2 * h + 0] + bv.x + rr.x;
                float v1 = acc[i][j][2 * h + 1] + bv.y + rr.y;
                acc[i][j][2 * h + 0] = v0;
                acc[i][j][2 * h + 1] = v1;
                *(float2*)(x2 + o) = make_float2(v0, v1);
                s1[tt] += v0 + v1;
                s2[tt] += v0 * v0 + v1 * v1;
            }
        }
    }
    // quad reduce (lanes sharing qrow)
    #pragma unroll
    for (int tt = 0; tt < 8; tt++) {
        s1[tt] += __shfl_xor_sync(0xffffffffu, s1[tt], 1);
        s1[tt] += __shfl_xor_sync(0xffffffffu, s1[tt], 2);
        s2[tt] += __shfl_xor_sync(0xffffffffu, s2[tt], 1);
        s2[tt] += __shfl_xor_sync(0xffffffffu, s2[tt], 2);
    }
    if ((lane & 3) == 0) {
        #pragma unroll
        for (int tt = 0; tt < 8; tt++) {
            red[wn * 64 + qrow + 8 * tt] = s1[tt];
            red[256 + wn * 64 + qrow + 8 * tt] = s2[tt];
        }
    }
    __syncthreads();
    if (t < 64) {
        float S1 = red[t] + red[64 + t] + red[128 + t] + red[192 + t];
        float S2 = red[256 + t] + red[320 + t] + red[384 + t] + red[448 + t];
        float m = S1 * (1.0f / 256.0f);
        float var = S2 * (1.0f / 256.0f) - m * m;
        red[512 + t] = m;
        red[576 + t] = rsqrtf(var + 1e-5f);
    }
    __syncthreads();

    // pass 2: y2 = (v - m) * rs * g + b
    #pragma unroll
    for (int i = 0; i < 4; i++) {
        #pragma unroll
        for (int j = 0; j < 8; j++) {
            int col = wn * 64 + j * 8 + qcol;
            float2 gv = *(const float2*)(g2 + col);
            float2 bv = *(const float2*)(be2 + col);
            #pragma unroll
            for (int h = 0; h < 2; h++) {
                int tt = i * 2 + h;
                int lr = qrow + 8 * tt;
                float m = red[512 + lr];
                float rs = red[576 + lr];
                size_t row = m0 + (size_t)lr;
                float y0 = (acc[i][j][2 * h + 0] - m) * rs * gv.x + bv.x;
                float y1 = (acc[i][j][2 * h + 1] - m) * rs * gv.y + bv.y;
                *(__nv_bfloat162*)(y2 + row * (size_t)NN + col) = __floats2bfloat162_rn(y0, y1);
            }
        }
    }
}

// ------------------------- Cosine attention -------------------------
#define STG_PITCH 385                 // uint32 words per staged row (384 + 1 pad)
#define KV_PITCH  36                  // floats per k/v row (32 + 4 pad)
#define KV_HEAD   (SEQ * KV_PITCH)    // 900 floats per head
#define ATTN_SMEM_WORDS (9632 + 2 * NHEAD * KV_HEAD)   // 24032
#define ATTN_SMEM_BYTES (ATTN_SMEM_WORDS * 4)          // 96128 B

__global__ __launch_bounds__(256) void attn_kernel(const float* __restrict__ logit_scale) {
    extern __shared__ float sm[];
    uint32_t* stage = (uint32_t*)sm;             // [25][385] words (bf16x2)
    float* kf = sm + 9632;                        // [8][25][36]
    float* vf = kf + NHEAD * KV_HEAD;             // [8][25][36]

    const int n = blockIdx.x;
    const int t = threadIdx.x;
    const int h = t >> 5;
    const int lane = t & 31;

    {
        const int4* gq = (const int4*)(g_qkv + (size_t)n * SEQ * D3);
        #pragma unroll
        for (int i = 0; i < 10; i++) {
            int idx = i * 256 + t;
            if (idx < 2400) {
                int r = idx / 96, c = idx % 96;
                int4 v4 = gq[r * 96 + c];
                uint32_t* d = stage + r * STG_PITCH + c * 4;
                d[0] = ((const uint32_t*)&v4)[0];
                d[1] = ((const uint32_t*)&v4)[1];
                d[2] = ((const uint32_t*)&v4)[2];
                d[3] = ((const uint32_t*)&v4)[3];
            }
        }
    }
    __syncthreads();

    float scale = expf(fminf(logit_scale[h], 4.6051701859880914f));  // log(100)
    float* khh = kf + h * KV_HEAD;
    float* vhh = vf + h * KV_HEAD;

    float q[32];
    if (lane < SEQ) {
        const uint32_t* row = stage + lane * STG_PITCH + h * 16;
        float kv[32], vv[32];
        float qs = 0.0f, ks = 0.0f;
        #pragma unroll
        for (int c = 0; c < 16; c++) {
            float2 fq = __bfloat1622float2(*(const __nv_bfloat162*)&row[c]);
            float2 fk = __bfloat1622float2(*(const __nv_bfloat162*)&row[c + 128]);
            float2 fv = __bfloat1622float2(*(const __nv_bfloat162*)&row[c + 256]);
            int d = c * 2;
            q[d] = fq.x;   q[d + 1] = fq.y;
            kv[d] = fk.x;  kv[d + 1] = fk.y;
            vv[d] = fv.x;  vv[d + 1] = fv.y;
            qs += fq.x * fq.x + fq.y * fq.y;
            ks += fk.x * fk.x + fk.y * fk.y;
        }
        float qf = scale * 0.17677669529663687f / fmaxf(sqrtf(qs), 1e-12f);
        float kf_ = 1.0f / fmaxf(sqrtf(ks), 1e-12f);
        float4* kp4 = (float4*)(khh + lane * KV_PITCH);
        float4* vp4 = (float4*)(vhh + lane * KV_PITCH);
        #pragma unroll
        for (int w = 0; w < 8; w++) {
            int d = w * 4;
            q[d] *= qf; q[d+1] *= qf; q[d+2] *= qf; q[d+3] *= qf;
            kp4[w] = make_float4(kv[d] * kf_, kv[d+1] * kf_, kv[d+2] * kf_, kv[d+3] * kf_);
            vp4[w] = make_float4(vv[d], vv[d+1], vv[d+2], vv[d+3]);
        }
    }
    __syncwarp();

    if (lane < SEQ) {
        float lg[SEQ];
        float mx = -1e30f;
        #pragma unroll
        for (int j = 0; j < SEQ; j++) {
            const float4* kp4 = (const float4*)(khh + j * KV_PITCH);
            float dot = 0.0f;
            #pragma unroll
            for (int tt = 0; tt < 8; tt++) {
                float4 kvv = kp4[tt];
                dot += q[tt * 4 + 0] * kvv.x + q[tt * 4 + 1] * kvv.y
                     + q[tt * 4 + 2] * kvv.z + q[tt * 4 + 3] * kvv.w;
            }
            lg[j] = dot;
            mx = fmaxf(mx, dot);
        }
        float ssum = 0.0f;
        #pragma unroll
        for (int j = 0; j < SEQ; j++) {
            lg[j] = expf(lg[j] - mx);
            ssum += lg[j];
        }
        float inv = 1.0f / ssum;

        float acc[32];
        #pragma unroll
        for (int d = 0; d < 32; d++) acc[d] = 0.0f;
        #pragma unroll
        for (int j = 0; j < SEQ; j++) {
            float a = lg[j];
            const float4* vp4 = (const float4*)(vhh + j * KV_PITCH);
            #pragma unroll
            for (int tt = 0; tt < 8; tt++) {
                float4 vvv = vp4[tt];
                acc[tt * 4 + 0] += a * vvv.x;
                acc[tt * 4 + 1] += a * vvv.y;
                acc[tt * 4 + 2] += a * vvv.z;
                acc[tt * 4 + 3] += a * vvv.w;
            }
        }
        union { int4 i4; __nv_bfloat162 h2[4]; } u;
        int4* op = (int4*)(g_attn + ((size_t)n * SEQ + lane) * DMODEL + h * HDIM);
        #pragma unroll
        for (int w = 0; w < 4; w++) {
            #pragma unroll
            for (int e = 0; e < 4; e++)
                u.h2[e] = __floats2bfloat162_rn(acc[w * 8 + 2 * e] * inv,
                                                acc[w * 8 + 2 * e + 1] * inv);
            op[w] = u.i4;
        }
    }
}

// ------------------------- launch -------------------------
extern "C" void kernel_launch(void* const* d_in, const int* in_sizes, int n_in,
                              void* d_out, int out_size) {
    const float* x           = (const float*)d_in[0];
    const float* ln1_g       = (const float*)d_in[1];
    const float* ln1_b       = (const float*)d_in[2];
    const float* qkv_w       = (const float*)d_in[3];
    const float* qkv_b       = (const float*)d_in[4];
    const float* proj_w      = (const float*)d_in[5];
    const float* proj_b      = (const float*)d_in[6];
    const float* logit_scale = (const float*)d_in[7];
    const float* ln2_g       = (const float*)d_in[8];
    const float* ln2_b       = (const float*)d_in[9];
    const float* w1          = (const float*)d_in[10];
    const float* b1          = (const float*)d_in[11];
    const float* w2          = (const float*)d_in[12];
    const float* b2          = (const float*)d_in[13];

    void *p_yb, *p_qkv, *p_attn, *p_x2, *p_y2, *p_hid, *p_wqkv, *p_wproj, *p_w1, *p_w2;
    cudaGetSymbolAddress(&p_yb, g_yb);
    cudaGetSymbolAddress(&p_qkv, g_qkv);
    cudaGetSymbolAddress(&p_attn, g_attn);
    cudaGetSymbolAddress(&p_x2, g_x2);
    cudaGetSymbolAddress(&p_y2, g_y2);
    cudaGetSymbolAddress(&p_hid, g_hid);
    cudaGetSymbolAddress(&p_wqkv, g_wqkv);
    cudaGetSymbolAddress(&p_wproj, g_wproj);
    cudaGetSymbolAddress(&p_w1, g_w1);
    cudaGetSymbolAddress(&p_w2, g_w2);

    cudaFuncSetAttribute(attn_kernel, cudaFuncAttributeMaxDynamicSharedMemorySize, ATTN_SMEM_BYTES);
    cudaFuncSetAttribute(mm_gemm<EPI_BF16>, cudaFuncAttributeMaxDynamicSharedMemorySize, GSMEM);
    cudaFuncSetAttribute(mm_gemm<EPI_GELU>, cudaFuncAttributeMaxDynamicSharedMemorySize, GSMEM);
    cudaFuncSetAttribute(mm_gemm<EPI_OUT>,  cudaFuncAttributeMaxDynamicSharedMemorySize, GSMEM);
    cudaFuncSetAttribute(proj_ln_gemm, cudaFuncAttributeMaxDynamicSharedMemorySize, PSMEM);

    // 1) weights -> bf16, transposed to [N,K] (coalesced tiled transpose)
    transpose_convert<<<dim3(D3 / 32, DMODEL / 32), dim3(32, 8)>>>(qkv_w, (__nv_bfloat16*)p_wqkv, DMODEL, D3);
    transpose_convert<<<dim3(DMODEL / 32, DMODEL / 32), dim3(32, 8)>>>(proj_w, (__nv_bfloat16*)p_wproj, DMODEL, DMODEL);
    transpose_convert<<<dim3(DFFN / 32, DMODEL / 32), dim3(32, 8)>>>(w1, (__nv_bfloat16*)p_w1, DMODEL, DFFN);
    transpose_convert<<<dim3(DMODEL / 32, DFFN / 32), dim3(32, 8)>>>(w2, (__nv_bfloat16*)p_w2, DFFN, DMODEL);
    // 2) LN1: x -> yb
    ln_kernel<<<NTOK / 8, 256>>>(x, ln1_g, ln1_b, (__nv_bfloat16*)p_yb);
    // 3) qkv GEMM: yb @ wqkv^T + b -> qkv (bf16)
    mm_gemm<EPI_BF16><<<dim3(D3 / 128, NTOK / 128), 128, GSMEM>>>(
        (const __nv_bfloat16*)p_yb, (const __nv_bfloat16*)p_wqkv, qkv_b, nullptr, p_qkv, D3, DMODEL);
    // 4) attention
    attn_kernel<<<NSEQ, 256, ATTN_SMEM_BYTES>>>(logit_scale);
    // 5) proj GEMM + residual + fused LN2 -> x2 (fp32) and y2 (bf16)
    proj_ln_gemm<<<NTOK / 64, 128, PSMEM>>>(
        (const __nv_bfloat16*)p_attn, (const __nv_bfloat16*)p_wproj, proj_b, x,
        ln2_g, ln2_b, (float*)p_x2, (__nv_bfloat16*)p_y2);
    // 6) ffn1 GEMM + gelu -> hid (bf16)
    mm_gemm<EPI_GELU><<<dim3(DFFN / 128, NTOK / 128), 128, GSMEM>>>(
        (const __nv_bfloat16*)p_y2, (const __nv_bfloat16*)p_w1, b1, nullptr, p_hid, DFFN, DMODEL);
    // 7) ffn2 GEMM + residual -> out (fp32)
    mm_gemm<EPI_OUT><<<dim3(DMODEL / 128, NTOK / 128), 128, GSMEM>>>(
        (const __nv_bfloat16*)p_hid, (const __nv_bfloat16*)p_w2, b2, (const float*)p_x2, d_out, DMODEL, DFFN);
}

// round 16
// speedup vs baseline: 1.1225x; 1.1225x over previous
#include <cuda_runtime.h>
#include <cuda_bf16.h>
#include <cuda_fp16.h>
#include <cstdint>
#include <math.h>

// Problem dims
#define NTOK   204800          // B*T*V = 64*128*25
#define NSEQ   8192            // B*T
#define SEQ    25
#define DMODEL 256
#define NHEAD  8
#define HDIM   32
#define DFFN   1024
#define D3     768

// ------------------------- scratch (device globals) -------------------------
__device__ __nv_bfloat16 g_yb  [(size_t)NTOK * DMODEL];
__device__ __nv_bfloat16 g_qkv [(size_t)NTOK * D3];
__device__ __nv_bfloat16 g_attn[(size_t)NTOK * DMODEL];
__device__ float         g_x2  [(size_t)NTOK * DMODEL];
__device__ __nv_bfloat16 g_y2  [(size_t)NTOK * DMODEL];
__device__ __nv_bfloat16 g_hid [(size_t)NTOK * DFFN];
// weights TRANSPOSED: [N, K] K-major
__device__ __nv_bfloat16 g_wqkv [D3   * DMODEL];
__device__ __nv_bfloat16 g_wproj[DMODEL * DMODEL];
__device__ __nv_bfloat16 g_w1   [DFFN * DMODEL];
__device__ __nv_bfloat16 g_w2   [DMODEL * DFFN];

// ------------------------- ptx helpers -------------------------
__device__ __forceinline__ void cp_async16(uint32_t smem_dst, const void* gmem_src) {
    asm volatile("cp.async.cg.shared.global [%0], [%1], 16;\n" :: "r"(smem_dst), "l"(gmem_src));
}
__device__ __forceinline__ void ldmatrix_x4(uint32_t& r0, uint32_t& r1, uint32_t& r2,
                                            uint32_t& r3, uint32_t addr) {
    asm volatile("ldmatrix.sync.aligned.m8n8.x4.shared.b16 {%0,%1,%2,%3}, [%4];"
                 : "=r"(r0), "=r"(r1), "=r"(r2), "=r"(r3) : "r"(addr));
}
__device__ __forceinline__ void ldmatrix_x4_trans(uint32_t& r0, uint32_t& r1, uint32_t& r2,
                                                  uint32_t& r3, uint32_t addr) {
    asm volatile("ldmatrix.sync.aligned.m8n8.x4.trans.shared.b16 {%0,%1,%2,%3}, [%4];"
                 : "=r"(r0), "=r"(r1), "=r"(r2), "=r"(r3) : "r"(addr));
}
__device__ __forceinline__ void mma16816(float& d0, float& d1, float& d2, float& d3,
                                         uint32_t a0, uint32_t a1, uint32_t a2, uint32_t a3,
                                         uint32_t b0, uint32_t b1) {
    asm volatile(
        "mma.sync.aligned.m16n8k16.row.col.f32.bf16.bf16.f32 "
        "{%0,%1,%2,%3}, {%4,%5,%6,%7}, {%8,%9}, {%0,%1,%2,%3};"
        : "+f"(d0), "+f"(d1), "+f"(d2), "+f"(d3)
        : "r"(a0), "r"(a1), "r"(a2), "r"(a3), "r"(b0), "r"(b1));
}
__device__ __forceinline__ void mma16816h(float& d0, float& d1, float& d2, float& d3,
                                          uint32_t a0, uint32_t a1, uint32_t a2, uint32_t a3,
                                          uint32_t b0, uint32_t b1) {
    asm volatile(
        "mma.sync.aligned.m16n8k16.row.col.f32.f16.f16.f32 "
        "{%0,%1,%2,%3}, {%4,%5,%6,%7}, {%8,%9}, {%0,%1,%2,%3};"
        : "+f"(d0), "+f"(d1), "+f"(d2), "+f"(d3)
        : "r"(a0), "r"(a1), "r"(a2), "r"(a3), "r"(b0), "r"(b1));
}
__device__ __forceinline__ uint32_t f2h2(float x, float y) {
    __half2 hh = __floats2half2_rn(x, y);
    return *(uint32_t*)&hh;
}
__device__ __forceinline__ float2 b2f2(uint32_t r) {
    return __bfloat1622float2(*(__nv_bfloat162*)&r);
}

// ------------------------- tiled transpose + fp32->bf16 convert -----------------
__global__ __launch_bounds__(256) void transpose_convert(const float* __restrict__ in,
                                                         __nv_bfloat16* __restrict__ out,
                                                         int K, int N) {
    __shared__ float tile[32][33];
    int n0 = blockIdx.x * 32, k0 = blockIdx.y * 32;
    int tx = threadIdx.x, ty = threadIdx.y;
    #pragma unroll
    for (int r = 0; r < 4; r++)
        tile[ty + r * 8][tx] = in[(size_t)(k0 + ty + r * 8) * N + n0 + tx];
    __syncthreads();
    #pragma unroll
    for (int r = 0; r < 4; r++)
        out[(size_t)(n0 + ty + r * 8) * K + k0 + tx] = __float2bfloat16(tile[tx][ty + r * 8]);
}

// ------------------------- LayerNorm (warp per row, D=256) -------------------------
__global__ __launch_bounds__(256) void ln_kernel(const float* __restrict__ X,
                                                 const float* __restrict__ gam,
                                                 const float* __restrict__ bet,
                                                 __nv_bfloat16* __restrict__ Y) {
    int warp = (blockIdx.x * blockDim.x + threadIdx.x) >> 5;
    int lane = threadIdx.x & 31;
    if (warp >= NTOK) return;
    const float4* xp = (const float4*)(X + (size_t)warp * DMODEL);
    float4 v0 = xp[lane * 2];
    float4 v1 = xp[lane * 2 + 1];
    float s = v0.x + v0.y + v0.z + v0.w + v1.x + v1.y + v1.z + v1.w;
    #pragma unroll
    for (int o = 16; o > 0; o >>= 1) s += __shfl_xor_sync(0xffffffffu, s, o);
    float m = s * (1.0f / 256.0f);
    float d0x = v0.x - m, d0y = v0.y - m, d0z = v0.z - m, d0w = v0.w - m;
    float d1x = v1.x - m, d1y = v1.y - m, d1z = v1.z - m, d1w = v1.w - m;
    float vs = d0x*d0x + d0y*d0y + d0z*d0z + d0w*d0w + d1x*d1x + d1y*d1y + d1z*d1z + d1w*d1w;
    #pragma unroll
    for (int o = 16; o > 0; o >>= 1) vs += __shfl_xor_sync(0xffffffffu, vs, o);
    float rstd = rsqrtf(vs * (1.0f / 256.0f) + 1e-5f);
    const float4* gp = (const float4*)gam;
    const float4* bp = (const float4*)bet;
    float4 g0 = gp[lane * 2], g1 = gp[lane * 2 + 1];
    float4 b0 = bp[lane * 2], b1 = bp[lane * 2 + 1];
    float y[8];
    y[0] = d0x * rstd * g0.x + b0.x;  y[1] = d0y * rstd * g0.y + b0.y;
    y[2] = d0z * rstd * g0.z + b0.z;  y[3] = d0w * rstd * g0.w + b0.w;
    y[4] = d1x * rstd * g1.x + b1.x;  y[5] = d1y * rstd * g1.y + b1.y;
    y[6] = d1z * rstd * g1.z + b1.z;  y[7] = d1w * rstd * g1.w + b1.w;
    union { int4 i4; __nv_bfloat162 h2[4]; } u;
    u.h2[0] = __floats2bfloat162_rn(y[0], y[1]);
    u.h2[1] = __floats2bfloat162_rn(y[2], y[3]);
    u.h2[2] = __floats2bfloat162_rn(y[4], y[5]);
    u.h2[3] = __floats2bfloat162_rn(y[6], y[7]);
    *((int4*)(Y + (size_t)warp * DMODEL + lane * 8)) = u.i4;
}

// ------------------------- mma.sync GEMM (generic) -------------------------
enum { EPI_BF16 = 0, EPI_PROJ = 1, EPI_GELU = 2, EPI_OUT = 3 };

#define ROWB   80
#define STAGE_A 10240
#define STAGE  20480
#define NSTAGE 4
#define GSMEM  (NSTAGE * STAGE)

template <int EPI>
__global__ __launch_bounds__(128) void mm_gemm(
    const __nv_bfloat16* __restrict__ A,
    const __nv_bfloat16* __restrict__ Bw,
    const float* __restrict__ bias,
    const float* __restrict__ res,
    void* __restrict__ out, int N, int K)
{
    extern __shared__ __align__(128) char smem[];
    const uint32_t sb = (uint32_t)__cvta_generic_to_shared(smem);
    const int t = threadIdx.x, wid = t >> 5, lane = t & 31;
    const int wm = wid & 1;
    const int wn = wid >> 1;
    const size_t m0 = (size_t)blockIdx.y * 128;
    const int n0 = blockIdx.x * 128;
    const int C = K >> 5;

    auto load_chunk = [&](int c, int s) {
        const uint32_t base = sb + (uint32_t)s * STAGE;
        const int k0 = c << 5;
        #pragma unroll
        for (int i = 0; i < 4; i++) {
            int idx = i * 128 + t;
            int r = idx >> 2, cc = idx & 3;
            cp_async16(base + (uint32_t)(r * ROWB + cc * 16),
                       A + (m0 + r) * K + k0 + cc * 8);
        }
        #pragma unroll
        for (int i = 0; i < 4; i++) {
            int idx = i * 128 + t;
            int r = idx >> 2, cc = idx & 3;
            cp_async16(base + STAGE_A + (uint32_t)(r * ROWB + cc * 16),
                       Bw + (size_t)(n0 + r) * K + k0 + cc * 8);
        }
        asm volatile("cp.async.commit_group;");
    };

    float acc[4][8][4];
    #pragma unroll
    for (int i = 0; i < 4; i++)
        #pragma unroll
        for (int j = 0; j < 8; j++)
            #pragma unroll
            for (int e = 0; e < 4; e++) acc[i][j][e] = 0.0f;

    load_chunk(0, 0);
    if (C > 1) load_chunk(1, 1);
    if (C > 2) load_chunk(2, 2);

    const int b_g = lane >> 3;
    const int b_row = lane & 7;
    const int b_noff = (b_g >> 1) * 8 + b_row;
    const int b_kc16 = (b_g & 1) * 16;

    for (int c = 0; c < C; c++) {
        if (c < C - 2)      { asm volatile("cp.async.wait_group 2;"); }
        else if (c == C - 2){ asm volatile("cp.async.wait_group 1;"); }
        else                { asm volatile("cp.async.wait_group 0;"); }
        __syncthreads();
        if (c + 3 < C) load_chunk(c + 3, (c + 3) & 3);

        const uint32_t aBase = sb + (uint32_t)(c & 3) * STAGE;
        const uint32_t bBase = aBase + STAGE_A;

        #pragma unroll
        for (int ks = 0; ks < 2; ks++) {
            uint32_t a[4][4];
            #pragma unroll
            for (int i = 0; i < 4; i++) {
                uint32_t addr = aBase
                    + (uint32_t)((wm * 64 + i * 16 + (lane & 15)) * ROWB
                                 + ks * 32 + (lane >> 4) * 16);
                ldmatrix_x4(a[i][0], a[i][1], a[i][2], a[i][3], addr);
            }
            uint32_t bb[8][2];
            #pragma unroll
            for (int g4 = 0; g4 < 4; g4++) {
                int nrow = wn * 64 + g4 * 16 + b_noff;
                uint32_t addr = bBase + (uint32_t)(nrow * ROWB + ks * 32 + b_kc16);
                ldmatrix_x4(bb[g4 * 2][0], bb[g4 * 2][1],
                            bb[g4 * 2 + 1][0], bb[g4 * 2 + 1][1], addr);
            }
            #pragma unroll
            for (int j = 0; j < 8; j++)
                #pragma unroll
                for (int i = 0; i < 4; i++)
                    mma16816(acc[i][j][0], acc[i][j][1], acc[i][j][2], acc[i][j][3],
                             a[i][0], a[i][1], a[i][2], a[i][3], bb[j][0], bb[j][1]);
        }
    }

    const int qrow = lane >> 2;
    const int qcol = (lane & 3) * 2;
    #pragma unroll
    for (int i = 0; i < 4; i++) {
        #pragma unroll
        for (int j = 0; j < 8; j++) {
            int col = n0 + wn * 64 + j * 8 + qcol;
            float2 bb = *(const float2*)(bias + col);
            #pragma unroll
            for (int h = 0; h < 2; h++) {
                size_t row = m0 + wm * 64 + i * 16 + qrow + h * 8;
                float v0 = acc[i][j][2 * h + 0] + bb.x;
                float v1 = acc[i][j][2 * h + 1] + bb.y;
                size_t o = row * (size_t)N + col;
                if (EPI == EPI_BF16) {
                    *(__nv_bfloat162*)((__nv_bfloat16*)out + o) = __floats2bfloat162_rn(v0, v1);
                } else if (EPI == EPI_GELU) {
                    v0 = 0.5f * v0 * (1.0f + erff(v0 * 0.70710678118654752f));
                    v1 = 0.5f * v1 * (1.0f + erff(v1 * 0.70710678118654752f));
                    *(__nv_bfloat162*)((__nv_bfloat16*)out + o) = __floats2bfloat162_rn(v0, v1);
                } else {
                    float2 rr = *(const float2*)(res + o);
                    float2 ov = make_float2(v0 + rr.x, v1 + rr.y);
                    *(float2*)((float*)out + o) = ov;
                }
            }
        }
    }
}

// ------------------------- Cosine attention on tensor cores -------------------------
// Block per sequence, warp per head. 25x25x32 per head padded to 32x32x32.
// QK^T: bf16 mma (q,k straight from staged smem via ldmatrix).
// P.V : fp16 mma (P packed fp16 from softmax; V via ldmatrix.trans, cvt to fp16).
// Stage pitch 388 words (== 4 mod 32) -> each 8-row ldmatrix group is
// bank-conflict-free. Pad rows 25..31 zeroed.
#define APITCH 388
#define AROWB  (APITCH * 4)             // 1552 bytes
#define ATTN_SMEM_BYTES (32 * AROWB + NHEAD * 32 * 4)   // 49664 + 1024 = 50688

__global__ __launch_bounds__(256) void attn_mma_kernel(const float* __restrict__ logit_scale) {
    extern __shared__ uint32_t asm_[];
    uint32_t* stage = asm_;                       // [32][388] words
    float* kfs = (float*)(asm_ + 32 * APITCH);    // [8][32]

    const int n = blockIdx.x;
    const int t = threadIdx.x;
    const int h = t >> 5;
    const int lane = t & 31;

    // ---- stage 25x768 bf16 qkv tile (coalesced), zero pad rows 25..31 ----
    {
        const int4* gq = (const int4*)(g_qkv + (size_t)n * SEQ * D3);
        #pragma unroll
        for (int i = 0; i < 10; i++) {
            int idx = i * 256 + t;
            if (idx < 2400) {
                int r = idx / 96, c = idx % 96;
                int4 v4 = gq[r * 96 + c];
                uint32_t* d = stage + r * APITCH + c * 4;
                d[0] = ((const uint32_t*)&v4)[0];
                d[1] = ((const uint32_t*)&v4)[1];
                d[2] = ((const uint32_t*)&v4)[2];
                d[3] = ((const uint32_t*)&v4)[3];
            }
        }
        #pragma unroll
        for (int i = 0; i < 11; i++) {
            int idx = i * 256 + t;
            if (idx < 7 * APITCH) stage[25 * APITCH + idx] = 0;
        }
    }
    __syncthreads();

    const uint32_t sb = (uint32_t)__cvta_generic_to_shared(stage);
    const uint32_t qb = sb + (uint32_t)h * 64;      // q words at h*16
    const uint32_t kb = qb + 512;                   // +128 words
    const uint32_t vb = qb + 1024;                  // +256 words

    // ---- A (q) fragments: 2 m-tiles x 2 k16-tiles ----
    uint32_t aq[2][2][4];
    #pragma unroll
    for (int i = 0; i < 2; i++)
        #pragma unroll
        for (int kt = 0; kt < 2; kt++) {
            uint32_t addr = qb + (uint32_t)((16 * i + (lane & 15)) * AROWB
                                            + kt * 32 + (lane >> 4) * 16);
            ldmatrix_x4(aq[i][kt][0], aq[i][kt][1], aq[i][kt][2], aq[i][kt][3], addr);
        }

    // ---- q row norms from fragments (quad covers all 32 cols) ----
    float qs[4] = {0.f, 0.f, 0.f, 0.f};
    #pragma unroll
    for (int i = 0; i < 2; i++)
        #pragma unroll
        for (int kt = 0; kt < 2; kt++) {
            #pragma unroll
            for (int j = 0; j < 4; j++) {
                float2 f = b2f2(aq[i][kt][j]);
                int s = 2 * i + (j & 1);
                qs[s] += f.x * f.x + f.y * f.y;
            }
        }
    #pragma unroll
    for (int s = 0; s < 4; s++) {
        qs[s] += __shfl_xor_sync(0xffffffffu, qs[s], 1);
        qs[s] += __shfl_xor_sync(0xffffffffu, qs[s], 2);
    }
    float scale = expf(fminf(logit_scale[h], 4.6051701859880914f));  // log(100)
    float qf[4];
    #pragma unroll
    for (int s = 0; s < 4; s++)
        qf[s] = scale * 0.17677669529663687f / fmaxf(sqrtf(qs[s]), 1e-12f);  // *1/sqrt(32)

    // ---- B (k) fragments: 4 n8-groups x 2 k16-tiles ----
    const int b_noff = ((lane >> 4) & 1) * 8 + (lane & 7);
    const int b_kc16 = ((lane >> 3) & 1) * 16;
    uint32_t bk[2][4][2];
    #pragma unroll
    for (int g2 = 0; g2 < 2; g2++)
        #pragma unroll
        for (int kt = 0; kt < 2; kt++) {
            uint32_t r0, r1, r2, r3;
            uint32_t addr = kb + (uint32_t)((16 * g2 + b_noff) * AROWB + kt * 32 + b_kc16);
            ldmatrix_x4(r0, r1, r2, r3, addr);
            bk[kt][2 * g2][0] = r0;  bk[kt][2 * g2][1] = r1;
            bk[kt][2 * g2 + 1][0] = r2;  bk[kt][2 * g2 + 1][1] = r3;
        }

    // ---- k col norms from fragments -> kfs smem ----
    {
        float ks[4] = {0.f, 0.f, 0.f, 0.f};
        #pragma unroll
        for (int g = 0; g < 4; g++)
            #pragma unroll
            for (int kt = 0; kt < 2; kt++)
                #pragma unroll
                for (int e = 0; e < 2; e++) {
                    float2 f = b2f2(bk[kt][g][e]);
                    ks[g] += f.x * f.x + f.y * f.y;
                }
        #pragma unroll
        for (int g = 0; g < 4; g++) {
            ks[g] += __shfl_xor_sync(0xffffffffu, ks[g], 1);
            ks[g] += __shfl_xor_sync(0xffffffffu, ks[g], 2);
        }
        if ((lane & 3) == 0) {
            #pragma unroll
            for (int g = 0; g < 4; g++)
                kfs[h * 32 + 8 * g + (lane >> 2)] = 1.0f / fmaxf(sqrtf(ks[g]), 1e-12f);
        }
    }
    __syncwarp();

    // ---- QK^T mma (bf16) ----
    float c[2][4][4];
    #pragma unroll
    for (int i = 0; i < 2; i++)
        #pragma unroll
        for (int g = 0; g < 4; g++)
            #pragma unroll
            for (int e = 0; e < 4; e++) c[i][g][e] = 0.0f;
    #pragma unroll
    for (int i = 0; i < 2; i++)
        #pragma unroll
        for (int g = 0; g < 4; g++)
            #pragma unroll
            for (int kt = 0; kt < 2; kt++)
                mma16816(c[i][g][0], c[i][g][1], c[i][g][2], c[i][g][3],
                         aq[i][kt][0], aq[i][kt][1], aq[i][kt][2], aq[i][kt][3],
                         bk[kt][g][0], bk[kt][g][1]);

    // ---- softmax + pack P to fp16 A-fragments ----
    float inv[2][2];
    uint32_t ap[2][2][4];
    #pragma unroll
    for (int i = 0; i < 2; i++) {
        float p0[8], p1[8];
        #pragma unroll
        for (int g = 0; g < 4; g++) {
            int col0 = 8 * g + 2 * (lane & 3);
            float kf0 = kfs[h * 32 + col0];
            float kf1 = kfs[h * 32 + col0 + 1];
            bool v0 = col0 < SEQ, v1 = (col0 + 1) < SEQ;
            p0[2 * g + 0] = v0 ? c[i][g][0] * qf[2 * i + 0] * kf0 : -1e30f;
            p0[2 * g + 1] = v1 ? c[i][g][1] * qf[2 * i + 0] * kf1 : -1e30f;
            p1[2 * g + 0] = v0 ? c[i][g][2] * qf[2 * i + 1] * kf0 : -1e30f;
            p1[2 * g + 1] = v1 ? c[i][g][3] * qf[2 * i + 1] * kf1 : -1e30f;
        }
        float mx0 = -1e30f, mx1 = -1e30f;
        #pragma unroll
        for (int e = 0; e < 8; e++) { mx0 = fmaxf(mx0, p0[e]); mx1 = fmaxf(mx1, p1[e]); }
        mx0 = fmaxf(mx0, __shfl_xor_sync(0xffffffffu, mx0, 1));
        mx0 = fmaxf(mx0, __shfl_xor_sync(0xffffffffu, mx0, 2));
        mx1 = fmaxf(mx1, __shfl_xor_sync(0xffffffffu, mx1, 1));
        mx1 = fmaxf(mx1, __shfl_xor_sync(0xffffffffu, mx1, 2));
        float s0 = 0.f, s1 = 0.f;
        #pragma unroll
        for (int e = 0; e < 8; e++) {
            p0[e] = expf(p0[e] - mx0); s0 += p0[e];
            p1[e] = expf(p1[e] - mx1); s1 += p1[e];
        }
        s0 += __shfl_xor_sync(0xffffffffu, s0, 1);
        s0 += __shfl_xor_sync(0xffffffffu, s0, 2);
        s1 += __shfl_xor_sync(0xffffffffu, s1, 1);
        s1 += __shfl_xor_sync(0xffffffffu, s1, 2);
        inv[i][0] = 1.0f / s0;
        inv[i][1] = 1.0f / s1;
        #pragma unroll
        for (int kt2 = 0; kt2 < 2; kt2++) {
            ap[i][kt2][0] = f2h2(p0[4 * kt2 + 0], p0[4 * kt2 + 1]);
            ap[i][kt2][1] = f2h2(p1[4 * kt2 + 0], p1[4 * kt2 + 1]);
            ap[i][kt2][2] = f2h2(p0[4 * kt2 + 2], p0[4 * kt2 + 3]);
            ap[i][kt2][3] = f2h2(p1[4 * kt2 + 2], p1[4 * kt2 + 3]);
        }
    }

    // ---- V B-fragments via ldmatrix.trans, convert bf16 -> fp16 ----
    uint32_t bv[2][4][2];   // [kt2 (j 16-block)][nh (hdim 8-group)][2]
    {
        const int vg = lane >> 3, vr = lane & 7;
        #pragma unroll
        for (int kt2 = 0; kt2 < 2; kt2++)
            #pragma unroll
            for (int nhalf = 0; nhalf < 2; nhalf++) {
                uint32_t r0, r1, r2, r3;
                int row = 16 * kt2 + (vg & 1) * 8 + vr;
                uint32_t addr = vb + (uint32_t)(row * AROWB + (vg >> 1) * 16 + nhalf * 32);
                ldmatrix_x4_trans(r0, r1, r2, r3, addr);
                bv[kt2][2 * nhalf][0] = r0;  bv[kt2][2 * nhalf][1] = r1;
                bv[kt2][2 * nhalf + 1][0] = r2;  bv[kt2][2 * nhalf + 1][1] = r3;
            }
        #pragma unroll
        for (int kt2 = 0; kt2 < 2; kt2++)
            #pragma unroll
            for (int nh = 0; nh < 4; nh++)
                #pragma unroll
                for (int e = 0; e < 2; e++) {
                    float2 f = b2f2(bv[kt2][nh][e]);
                    bv[kt2][nh][e] = f2h2(f.x, f.y);
                }
    }

    // ---- P @ V mma (fp16) ----
    float co[2][4][4];
    #pragma unroll
    for (int i = 0; i < 2; i++)
        #pragma unroll
        for (int nh = 0; nh < 4; nh++)
            #pragma unroll
            for (int e = 0; e < 4; e++) co[i][nh][e] = 0.0f;
    #pragma unroll
    for (int i = 0; i < 2; i++)
        #pragma unroll
        for (int nh = 0; nh < 4; nh++)
            #pragma unroll
            for (int kt2 = 0; kt2 < 2; kt2++)
                mma16816h(co[i][nh][0], co[i][nh][1], co[i][nh][2], co[i][nh][3],
                          ap[i][kt2][0], ap[i][kt2][1], ap[i][kt2][2], ap[i][kt2][3],
                          bv[kt2][nh][0], bv[kt2][nh][1]);

    // ---- store (rows < 25 only) ----
    #pragma unroll
    for (int i = 0; i < 2; i++) {
        int r0 = 16 * i + (lane >> 2);
        int r1 = r0 + 8;
        #pragma unroll
        for (int nh = 0; nh < 4; nh++) {
            int col = h * HDIM + 8 * nh + 2 * (lane & 3);
            if (r0 < SEQ)
                *(__nv_bfloat162*)(g_attn + ((size_t)n * SEQ + r0) * DMODEL + col) =
                    __floats2bfloat162_rn(co[i][nh][0] * inv[i][0], co[i][nh][1] * inv[i][0]);
            if (r1 < SEQ)
                *(__nv_bfloat162*)(g_attn + ((size_t)n * SEQ + r1) * DMODEL + col) =
                    __floats2bfloat162_rn(co[i][nh][2] * inv[i][1], co[i][nh][3] * inv[i][1]);
        }
    }
}

// ------------------------- launch -------------------------
extern "C" void kernel_launch(void* const* d_in, const int* in_sizes, int n_in,
                              void* d_out, int out_size) {
    const float* x           = (const float*)d_in[0];
    const float* ln1_g       = (const float*)d_in[1];
    const float* ln1_b       = (const float*)d_in[2];
    const float* qkv_w       = (const float*)d_in[3];
    const float* qkv_b       = (const float*)d_in[4];
    const float* proj_w      = (const float*)d_in[5];
    const float* proj_b      = (const float*)d_in[6];
    const float* logit_scale = (const float*)d_in[7];
    const float* ln2_g       = (const float*)d_in[8];
    const float* ln2_b       = (const float*)d_in[9];
    const float* w1          = (const float*)d_in[10];
    const float* b1          = (const float*)d_in[11];
    const float* w2          = (const float*)d_in[12];
    const float* b2          = (const float*)d_in[13];

    void *p_yb, *p_qkv, *p_attn, *p_x2, *p_y2, *p_hid, *p_wqkv, *p_wproj, *p_w1, *p_w2;
    cudaGetSymbolAddress(&p_yb, g_yb);
    cudaGetSymbolAddress(&p_qkv, g_qkv);
    cudaGetSymbolAddress(&p_attn, g_attn);
    cudaGetSymbolAddress(&p_x2, g_x2);
    cudaGetSymbolAddress(&p_y2, g_y2);
    cudaGetSymbolAddress(&p_hid, g_hid);
    cudaGetSymbolAddress(&p_wqkv, g_wqkv);
    cudaGetSymbolAddress(&p_wproj, g_wproj);
    cudaGetSymbolAddress(&p_w1, g_w1);
    cudaGetSymbolAddress(&p_w2, g_w2);

    cudaFuncSetAttribute(attn_mma_kernel, cudaFuncAttributeMaxDynamicSharedMemorySize, ATTN_SMEM_BYTES);
    cudaFuncSetAttribute(mm_gemm<EPI_BF16>, cudaFuncAttributeMaxDynamicSharedMemorySize, GSMEM);
    cudaFuncSetAttribute(mm_gemm<EPI_PROJ>, cudaFuncAttributeMaxDynamicSharedMemorySize, GSMEM);
    cudaFuncSetAttribute(mm_gemm<EPI_GELU>, cudaFuncAttributeMaxDynamicSharedMemorySize, GSMEM);
    cudaFuncSetAttribute(mm_gemm<EPI_OUT>,  cudaFuncAttributeMaxDynamicSharedMemorySize, GSMEM);

    // 1) weights -> bf16, transposed to [N,K]
    transpose_convert<<<dim3(D3 / 32, DMODEL / 32), dim3(32, 8)>>>(qkv_w, (__nv_bfloat16*)p_wqkv, DMODEL, D3);
    transpose_convert<<<dim3(DMODEL / 32, DMODEL / 32), dim3(32, 8)>>>(proj_w, (__nv_bfloat16*)p_wproj, DMODEL, DMODEL);
    transpose_convert<<<dim3(DFFN / 32, DMODEL / 32), dim3(32, 8)>>>(w1, (__nv_bfloat16*)p_w1, DMODEL, DFFN);
    transpose_convert<<<dim3(DMODEL / 32, DFFN / 32), dim3(32, 8)>>>(w2, (__nv_bfloat16*)p_w2, DFFN, DMODEL);
    // 2) LN1: x -> yb
    ln_kernel<<<NTOK / 8, 256>>>(x, ln1_g, ln1_b, (__nv_bfloat16*)p_yb);
    // 3) qkv GEMM
    mm_gemm<EPI_BF16><<<dim3(D3 / 128, NTOK / 128), 128, GSMEM>>>(
        (const __nv_bfloat16*)p_yb, (const __nv_bfloat16*)p_wqkv, qkv_b, nullptr, p_qkv, D3, DMODEL);
    // 4) attention (tensor-core)
    attn_mma_kernel<<<NSEQ, 256, ATTN_SMEM_BYTES>>>(logit_scale);
    // 5) proj GEMM + residual -> x2 (fp32)
    mm_gemm<EPI_PROJ><<<dim3(DMODEL / 128, NTOK / 128), 128, GSMEM>>>(
        (const __nv_bfloat16*)p_attn, (const __nv_bfloat16*)p_wproj, proj_b, x, p_x2, DMODEL, DMODEL);
    // 6) LN2: x2 -> y2
    ln_kernel<<<NTOK / 8, 256>>>((const float*)p_x2, ln2_g, ln2_b, (__nv_bfloat16*)p_y2);
    // 7) ffn1 GEMM + gelu -> hid (bf16)
    mm_gemm<EPI_GELU><<<dim3(DFFN / 128, NTOK / 128), 128, GSMEM>>>(
        (const __nv_bfloat16*)p_y2, (const __nv_bfloat16*)p_w1, b1, nullptr, p_hid, DFFN, DMODEL);
    // 8) ffn2 GEMM + residual -> out (fp32)
    mm_gemm<EPI_OUT><<<dim3(DMODEL / 128, NTOK / 128), 128, GSMEM>>>(
        (const __nv_bfloat16*)p_hid, (const __nv_bfloat16*)p_w2, b2, (const float*)p_x2, d_out, DMODEL, DFFN);
}